// round 16
// baseline (speedup 1.0000x reference)
#include <cuda_runtime.h>
#include <cuda_fp16.h>
#include <cstdint>
#include <math.h>

// Problem constants
#define BB 2
#define LL 2048
#define DDIM 1024
#define HH 16
#define HDIM 64
#define MM (BB*LL)          // 4096 rows
#define WIN 512
#define DIL 2

// Scratch (device globals; no allocation allowed)
__device__ __half g_h[(size_t)MM*DDIM];          // LN output (fp16)
__device__ __half g_qkv[(size_t)MM*3*DDIM];      // QKV (fp16)
__device__ __half g_attn[(size_t)MM*DDIM];       // attention output (fp16)
__device__ float  g_x1[(size_t)MM*DDIM];         // x + attn@Wout (fp32, residual)
__device__ __half g_f[(size_t)MM*4*DDIM];        // FFN hidden (fp16)
__device__ __half g_wt[(size_t)12582912];        // fp16 weights, SAME [K,N] layout
#define WT_QKV 0
#define WT_OUT 3145728
#define WT_W1  4194304
#define WT_W2  8388608
#define WT_END 12582912
#define NCONVB 3072                               // convert blocks (WT_END/4096)

__device__ __forceinline__ void pdl_wait() {
#if __CUDA_ARCH__ >= 900
    cudaGridDependencySynchronize();
#endif
}
__device__ __forceinline__ void pdl_trigger() {
#if __CUDA_ARCH__ >= 900
    cudaTriggerProgrammaticLaunchCompletion();
#endif
}

__device__ __forceinline__ void mma_fp16(float d[4], const uint32_t a[4],
                                         uint32_t b0, uint32_t b1) {
    asm volatile(
        "mma.sync.aligned.m16n8k16.row.col.f32.f16.f16.f32 "
        "{%0,%1,%2,%3}, {%4,%5,%6,%7}, {%8,%9}, {%0,%1,%2,%3};\n"
        : "+f"(d[0]), "+f"(d[1]), "+f"(d[2]), "+f"(d[3])
        : "r"(a[0]), "r"(a[1]), "r"(a[2]), "r"(a[3]),
          "r"(b0), "r"(b1));
}

__device__ __forceinline__ void ldsm_x4(uint32_t r[4], uint32_t addr) {
    asm volatile("ldmatrix.sync.aligned.m8n8.x4.shared.b16 {%0,%1,%2,%3}, [%4];"
                 : "=r"(r[0]), "=r"(r[1]), "=r"(r[2]), "=r"(r[3]) : "r"(addr));
}
__device__ __forceinline__ void ldsm_x4_t(uint32_t r[4], uint32_t addr) {
    asm volatile("ldmatrix.sync.aligned.m8n8.x4.trans.shared.b16 {%0,%1,%2,%3}, [%4];"
                 : "=r"(r[0]), "=r"(r[1]), "=r"(r[2]), "=r"(r[3]) : "r"(addr));
}

__device__ __forceinline__ float gelu_exact(float x) {
    return 0.5f * x * (1.0f + erff(x * 0.70710678118654752f));
}

__device__ __forceinline__ void cp_async16(uint32_t smem_addr, const void* gptr) {
    asm volatile("cp.async.cg.shared.global [%0], [%1], 16;\n"
                 :: "r"(smem_addr), "l"(gptr));
}
__device__ __forceinline__ void cp_commit() {
    asm volatile("cp.async.commit_group;\n");
}
__device__ __forceinline__ void cp_wait2() {
    asm volatile("cp.async.wait_group 2;\n");
}
__device__ __forceinline__ void cp_wait1() {
    asm volatile("cp.async.wait_group 1;\n");
}
__device__ __forceinline__ uint32_t smem_u32(const void* p) {
    uint32_t a;
    asm("{ .reg .u64 t; cvta.to.shared.u64 t, %1; cvt.u32.u64 %0, t; }"
        : "=r"(a) : "l"(p));
    return a;
}

__device__ __forceinline__ void store2(__half* p, float a, float b) {
    *reinterpret_cast<__half2*>(p) = __floats2half2_rn(a, b);
}
__device__ __forceinline__ void store2(float* p, float a, float b) {
    *reinterpret_cast<float2*>(p) = make_float2(a, b);
}

__device__ __forceinline__ uint32_t pack_h2(float a, float b) {
    __half2 h = __floats2half2_rn(a, b);
    return *reinterpret_cast<uint32_t*>(&h);
}

// ---------------------------------------------------------------------------
// Fused: LN1 (blocks 0..MM-1) + weight fp32->fp16 convert (blocks MM..)
// ---------------------------------------------------------------------------
__global__ void ln_conv_kernel(const float* __restrict__ x, const float* __restrict__ g,
                               const float* __restrict__ b, __half* __restrict__ out,
                               const float* __restrict__ s0, const float* __restrict__ s1,
                               const float* __restrict__ s2, const float* __restrict__ s3,
                               __half* __restrict__ wdst) {
    if (blockIdx.x >= MM) {
        size_t i = ((size_t)(blockIdx.x - MM) * 256 + threadIdx.x) * 16;
        const float* src; size_t base;
        if (i < WT_OUT)      { src = s0; base = 0; }
        else if (i < WT_W1)  { src = s1; base = WT_OUT; }
        else if (i < WT_W2)  { src = s2; base = WT_W1; }
        else                 { src = s3; base = WT_W2; }
        const float* sp = src + (i - base);
        float4 a0 = *reinterpret_cast<const float4*>(sp);
        float4 a1 = *reinterpret_cast<const float4*>(sp + 4);
        float4 a2 = *reinterpret_cast<const float4*>(sp + 8);
        float4 a3 = *reinterpret_cast<const float4*>(sp + 12);
        uint4 p0, p1;
        p0.x = pack_h2(a0.x, a0.y); p0.y = pack_h2(a0.z, a0.w);
        p0.z = pack_h2(a1.x, a1.y); p0.w = pack_h2(a1.z, a1.w);
        p1.x = pack_h2(a2.x, a2.y); p1.y = pack_h2(a2.z, a2.w);
        p1.z = pack_h2(a3.x, a3.y); p1.w = pack_h2(a3.z, a3.w);
        *reinterpret_cast<uint4*>(wdst + i) = p0;
        *reinterpret_cast<uint4*>(wdst + i + 8) = p1;
        return;
    }
    int row = blockIdx.x;
    int t = threadIdx.x;
    const float4 xv = reinterpret_cast<const float4*>(x + (size_t)row * DDIM)[t];

    __shared__ float warp_s[8], warp_q[8];
    __shared__ float s_mu, s_r;

    float s = xv.x + xv.y + xv.z + xv.w;
    float q = xv.x*xv.x + xv.y*xv.y + xv.z*xv.z + xv.w*xv.w;
#pragma unroll
    for (int o = 16; o; o >>= 1) {
        s += __shfl_xor_sync(~0u, s, o);
        q += __shfl_xor_sync(~0u, q, o);
    }
    if ((t & 31) == 0) { warp_s[t >> 5] = s; warp_q[t >> 5] = q; }
    __syncthreads();
    if (t == 0) {
        float S = 0.f, Q = 0.f;
#pragma unroll
        for (int i = 0; i < 8; i++) { S += warp_s[i]; Q += warp_q[i]; }
        float mu = S * (1.0f / DDIM);
        float var = Q * (1.0f / DDIM) - mu * mu;
        s_mu = mu;
        s_r = rsqrtf(var + 1e-5f);
    }
    __syncthreads();
    float mu = s_mu, r = s_r;
    float4 gv = reinterpret_cast<const float4*>(g)[t];
    float4 bv = reinterpret_cast<const float4*>(b)[t];
    uint2 pk;
    pk.x = pack_h2((xv.x - mu) * r * gv.x + bv.x, (xv.y - mu) * r * gv.y + bv.y);
    pk.y = pack_h2((xv.z - mu) * r * gv.z + bv.z, (xv.w - mu) * r * gv.w + bv.w);
    *reinterpret_cast<uint2*>(out + (size_t)row * DDIM + t * 4) = pk;
}

// ---------------------------------------------------------------------------
// LayerNorm (standalone, for LN2).  PDL: wait at entry, trigger after stats.
// ---------------------------------------------------------------------------
__global__ void ln_kernel(const float* __restrict__ x, const float* __restrict__ g,
                          const float* __restrict__ b, __half* __restrict__ out) {
    pdl_wait();
    int row = blockIdx.x;
    int t = threadIdx.x;
    const float4 xv = reinterpret_cast<const float4*>(x + (size_t)row * DDIM)[t];

    __shared__ float warp_s[8], warp_q[8];
    __shared__ float s_mu, s_r;

    float s = xv.x + xv.y + xv.z + xv.w;
    float q = xv.x*xv.x + xv.y*xv.y + xv.z*xv.z + xv.w*xv.w;
#pragma unroll
    for (int o = 16; o; o >>= 1) {
        s += __shfl_xor_sync(~0u, s, o);
        q += __shfl_xor_sync(~0u, q, o);
    }
    if ((t & 31) == 0) { warp_s[t >> 5] = s; warp_q[t >> 5] = q; }
    __syncthreads();
    if (t == 0) {
        float S = 0.f, Q = 0.f;
#pragma unroll
        for (int i = 0; i < 8; i++) { S += warp_s[i]; Q += warp_q[i]; }
        float mu = S * (1.0f / DDIM);
        float var = Q * (1.0f / DDIM) - mu * mu;
        s_mu = mu;
        s_r = rsqrtf(var + 1e-5f);
    }
    __syncthreads();
    pdl_trigger();
    float mu = s_mu, r = s_r;
    float4 gv = reinterpret_cast<const float4*>(g)[t];
    float4 bv = reinterpret_cast<const float4*>(b)[t];
    uint2 pk;
    pk.x = pack_h2((xv.x - mu) * r * gv.x + bv.x, (xv.y - mu) * r * gv.y + bv.y);
    pk.y = pack_h2((xv.z - mu) * r * gv.z + bv.z, (xv.w - mu) * r * gv.w + bv.w);
    *reinterpret_cast<uint2*>(out + (size_t)row * DDIM + t * 4) = pk;
}

// ---------------------------------------------------------------------------
// FP16 GEMM — mainloop BYTE-IDENTICAL to round-14 best. PDL is loop-invariant:
// pdl_wait() before the prologue fill; pdl_trigger() before the epilogue.
// CTA tile 128x128x32, 128 threads (4 warps), warp tile 64x64, m16n8k16.
// A: [128 m][32 k] pitch 80B; B: [32 k][128 n] pitch 272B, ldmatrix.x4.trans.
// 4-stage cp.async, wait_group 2, 2 CTA/SM.
// ---------------------------------------------------------------------------
#define ASTG 10240                    // A stage bytes: 128 rows * 80B
#define BSTG 8704                     // B stage bytes: 32 rows * 272B
#define FNST 4
#define FSMEM (FNST*(ASTG+BSTG))      // 75776 bytes

template <int EPI, typename OUT>
__global__ void __launch_bounds__(128, 2)
gemm_fp16(const __half* __restrict__ A, const __half* __restrict__ W,
          const float* __restrict__ bias, const float* __restrict__ res,
          OUT* __restrict__ C, int M, int N, int K) {
    extern __shared__ char dsm[];
    uint32_t base = smem_u32(dsm);
    uint32_t bBase = base + FNST * ASTG;

    int tid = threadIdx.x;
    int warp = tid >> 5, lane = tid & 31;
    int wm = warp & 1;     // 2 warps along M -> 64 rows
    int wn = warp >> 1;    // 2 warps along N -> 64 cols
    int mrow = lane >> 2, kq = lane & 3;
    int m0 = blockIdx.y * 128, n0 = blockIdx.x * 128;

    const __half* agp[4];
    const __half* bgp[4];
    uint32_t adst[4], bdst[4];
#pragma unroll
    for (int i = 0; i < 4; i++) {
        int ca = tid + i * 128;
        int ar = ca >> 2, ac = (ca & 3) * 8;
        agp[i] = A + (size_t)(m0 + ar) * K + ac;
        adst[i] = base + ar * 80 + ac * 2;
        int br = ca >> 4, bc = (ca & 15) * 8;
        bgp[i] = W + (size_t)br * N + n0 + bc;
        bdst[i] = bBase + br * 272 + bc * 2;
    }

    float acc[4][8][4];
#pragma unroll
    for (int i = 0; i < 4; i++)
#pragma unroll
        for (int j = 0; j < 8; j++)
#pragma unroll
            for (int k = 0; k < 4; k++) acc[i][j][k] = 0.f;

    int nk = K / 32;
    auto issue = [&](int it) {
        if (it < nk) {
            int s = it & 3;
            int k0 = it * 32;
#pragma unroll
            for (int i = 0; i < 4; i++) {
                cp_async16(adst[i] + s * ASTG, agp[i] + k0);
                cp_async16(bdst[i] + s * BSTG, bgp[i] + (size_t)k0 * N);
            }
        }
        cp_commit();
    };

    pdl_wait();   // predecessor complete; prologue fill follows (round-14 exact)
    issue(0); issue(1); issue(2);

    int lrow = lane & 15;
    int lcolB = (lane >> 4) * 16;

    for (int it = 0; it < nk; it++) {
        cp_wait2();
        __syncthreads();
        issue(it + 3);
        int s = it & 3;
        uint32_t aST = base + s * ASTG;
        uint32_t bST = bBase + s * BSTG;
#pragma unroll
        for (int ks = 0; ks < 32; ks += 16) {
            uint32_t a[4][4], b[4][4];
#pragma unroll
            for (int fm = 0; fm < 4; fm++)
                ldsm_x4(a[fm], aST + (wm * 64 + fm * 16 + lrow) * 80 + ks * 2 + lcolB);
            uint32_t bRow = bST + (ks + lrow) * 272 + lcolB;
#pragma unroll
            for (int p = 0; p < 4; p++)
                ldsm_x4_t(b[p], bRow + (wn * 64 + p * 16) * 2);
#pragma unroll
            for (int fm = 0; fm < 4; fm++)
#pragma unroll
                for (int fn = 0; fn < 8; fn++)
                    mma_fp16(acc[fm][fn], a[fm],
                             b[fn >> 1][(fn & 1) * 2], b[fn >> 1][(fn & 1) * 2 + 1]);
        }
    }

    pdl_trigger();   // successor may launch while we run the epilogue

#pragma unroll
    for (int fm = 0; fm < 4; fm++) {
#pragma unroll
        for (int fn = 0; fn < 8; fn++) {
            int mr = m0 + wm * 64 + fm * 16 + mrow;
            int nc = n0 + wn * 64 + fn * 8 + (kq << 1);
            float bx = bias[nc], by = bias[nc + 1];
            float v0 = acc[fm][fn][0] + bx;
            float v1 = acc[fm][fn][1] + by;
            float v2 = acc[fm][fn][2] + bx;
            float v3 = acc[fm][fn][3] + by;
            if (EPI == 1) {
                v0 += res[(size_t)mr * N + nc];
                v1 += res[(size_t)mr * N + nc + 1];
                v2 += res[(size_t)(mr + 8) * N + nc];
                v3 += res[(size_t)(mr + 8) * N + nc + 1];
            } else if (EPI == 2) {
                v0 = gelu_exact(v0); v1 = gelu_exact(v1);
                v2 = gelu_exact(v2); v3 = gelu_exact(v3);
            }
            store2(C + (size_t)mr * N + nc, v0, v1);
            store2(C + (size_t)(mr + 8) * N + nc, v2, v3);
        }
    }
}

// ---------------------------------------------------------------------------
// Flash attention, parity streams, fp16 MMA datapath.
// 3-stage K/V cp.async ring, issue at loop top.
// PDL: wait at entry, trigger before output stores.
// ---------------------------------------------------------------------------
#define ATP 72    // smem pitch in halves (144 B)
#define KVST (32 * ATP * 2)   // bytes per K (or V) tile buffer

__global__ void __launch_bounds__(128, 4)
attn_flash(const __half* __restrict__ qkv, __half* __restrict__ out) {
    __shared__ __half Qs[64 * ATP];
    __shared__ __half Ks[3][32 * ATP];
    __shared__ __half Vs[3][32 * ATP];

    pdl_wait();

    int tid = threadIdx.x;
    int w = tid >> 5, lane = tid & 31;
    int mrow = lane >> 2;
    int kq = lane & 3;

    int qt0 = blockIdx.x * 64;
    int y = blockIdx.y;
    int p = y & 1, h = (y >> 1) & 15, b = y >> 5;

    {
        int r = tid >> 1;
        int d0 = (tid & 1) * 32;
        int l = 2 * (qt0 + r) + p;
        const __half* src = qkv + ((size_t)(b * LL + l)) * (3 * DDIM) + h * HDIM + d0;
        __half* dst = Qs + r * ATP + d0;
        const __half2 sc = __float2half2_rn(0.125f);
#pragma unroll
        for (int i = 0; i < 4; i++) {
            uint4 v = reinterpret_cast<const uint4*>(src)[i];
            __half2* hv = reinterpret_cast<__half2*>(&v);
#pragma unroll
            for (int j = 0; j < 4; j++) hv[j] = __hmul2(hv[j], sc);
            reinterpret_cast<uint4*>(dst)[i] = v;
        }
    }

    int ktbeg = qt0 - 256; if (ktbeg < 0) ktbeg = 0;
    int nt = (qt0 + 32 - ktbeg) / 32 + 1;

    int kvr0 = tid >> 3;
    int kvc = (tid & 7) * 16;
    uint32_t ksb = smem_u32(Ks);
    uint32_t vsb = smem_u32(Vs);
    auto issue_kv = [&](int ti) {
        if (ti < nt) {
            int s = ti % 3;
            int kt0 = ktbeg + ti * 32;
#pragma unroll
            for (int half = 0; half < 2; half++) {
                int r = kvr0 + half * 16;
                int lk = 2 * (kt0 + r) + p;
                const __half* kb = qkv + ((size_t)(b * LL + lk)) * (3 * DDIM)
                                   + DDIM + h * HDIM;
                cp_async16(ksb + s * KVST + r * 144 + kvc,
                           reinterpret_cast<const char*>(kb) + kvc);
                cp_async16(vsb + s * KVST + r * 144 + kvc,
                           reinterpret_cast<const char*>(kb + DDIM) + kvc);
            }
        }
        cp_commit();
    };
    issue_kv(0);
    issue_kv(1);

    __syncthreads();   // Q tile ready

    uint32_t qa[4][4];
    {
        uint32_t qb = smem_u32(Qs) + (w * 16 + (lane & 15)) * (ATP * 2) + (lane >> 4) * 16;
#pragma unroll
        for (int i = 0; i < 4; i++) ldsm_x4(qa[i], qb + i * 32);
    }

    float m_lo = -1e30f, m_hi = -1e30f, l_lo = 0.f, l_hi = 0.f;
    float o[8][4];
#pragma unroll
    for (int i = 0; i < 8; i++)
#pragma unroll
        for (int j = 0; j < 4; j++) o[i][j] = 0.f;

    int tq_lo = qt0 + 16 * w + mrow;
    int tq_hi = tq_lo + 8;

    uint32_t kaddrO = ((lane >> 4) * 8 + (lane & 7)) * (ATP * 2) + ((lane >> 3) & 1) * 16;
    uint32_t vaddrO = (lane & 15) * (ATP * 2) + (lane >> 4) * 16;

    for (int ti = 0; ti < nt; ti++) {
        int kt0 = ktbeg + ti * 32;
        int s = ti % 3;
        cp_wait1();
        __syncthreads();           // orders prev iter's reads before new writes
        issue_kv(ti + 2);          // writes stage (ti+2)%3 — disjoint from ti, ti+1
        uint32_t kaddr = ksb + s * KVST + kaddrO;
        uint32_t vaddr = vsb + s * KVST + vaddrO;

        float s_acc[4][4];
#pragma unroll
        for (int fn = 0; fn < 4; fn++)
#pragma unroll
            for (int j = 0; j < 4; j++) s_acc[fn][j] = 0.f;
#pragma unroll
        for (int i = 0; i < 4; i++) {
            uint32_t kb0[4], kb1[4];
            ldsm_x4(kb0, kaddr + i * 32);
            ldsm_x4(kb1, kaddr + 16 * (ATP * 2) + i * 32);
            mma_fp16(s_acc[0], qa[i], kb0[0], kb0[1]);
            mma_fp16(s_acc[1], qa[i], kb0[2], kb0[3]);
            mma_fp16(s_acc[2], qa[i], kb1[0], kb1[1]);
            mma_fp16(s_acc[3], qa[i], kb1[2], kb1[3]);
        }

        bool needmask = (kt0 > qt0 + 16 * w - 31) || (kt0 < qt0 + 16 * w - 241);

        float mt_lo = -1e30f, mt_hi = -1e30f;
        if (needmask) {
#pragma unroll
            for (int fn = 0; fn < 4; fn++) {
#pragma unroll
                for (int j = 0; j < 2; j++) {
                    int tk = kt0 + 8 * fn + 2 * kq + j;
                    if (!(tk <= tq_lo && tq_lo - tk <= 256)) s_acc[fn][j] = -1e30f;
                    if (!(tk <= tq_hi && tq_hi - tk <= 256)) s_acc[fn][2 + j] = -1e30f;
                    mt_lo = fmaxf(mt_lo, s_acc[fn][j]);
                    mt_hi = fmaxf(mt_hi, s_acc[fn][2 + j]);
                }
            }
        } else {
#pragma unroll
            for (int fn = 0; fn < 4; fn++) {
                mt_lo = fmaxf(mt_lo, fmaxf(s_acc[fn][0], s_acc[fn][1]));
                mt_hi = fmaxf(mt_hi, fmaxf(s_acc[fn][2], s_acc[fn][3]));
            }
        }
        mt_lo = fmaxf(mt_lo, __shfl_xor_sync(~0u, mt_lo, 1));
        mt_lo = fmaxf(mt_lo, __shfl_xor_sync(~0u, mt_lo, 2));
        mt_hi = fmaxf(mt_hi, __shfl_xor_sync(~0u, mt_hi, 1));
        mt_hi = fmaxf(mt_hi, __shfl_xor_sync(~0u, mt_hi, 2));
        float mn_lo = fmaxf(m_lo, mt_lo);
        float mn_hi = fmaxf(m_hi, mt_hi);
        float cf_lo = __expf(m_lo - mn_lo);
        float cf_hi = __expf(m_hi - mn_hi);
        m_lo = mn_lo; m_hi = mn_hi;

        float rs_lo = 0.f, rs_hi = 0.f;
        uint32_t pa[2][4];
        if (needmask) {
#pragma unroll
            for (int fn = 0; fn < 4; fn++) {
                float p0 = __expf(s_acc[fn][0] - mn_lo);
                float p1 = __expf(s_acc[fn][1] - mn_lo);
                float p2 = __expf(s_acc[fn][2] - mn_hi);
                float p3 = __expf(s_acc[fn][3] - mn_hi);
                if (s_acc[fn][0] < -1e29f) p0 = 0.f;
                if (s_acc[fn][1] < -1e29f) p1 = 0.f;
                if (s_acc[fn][2] < -1e29f) p2 = 0.f;
                if (s_acc[fn][3] < -1e29f) p3 = 0.f;
                rs_lo += p0 + p1; rs_hi += p2 + p3;
                pa[fn >> 1][(fn & 1) * 2] = pack_h2(p0, p1);
                pa[fn >> 1][(fn & 1) * 2 + 1] = pack_h2(p2, p3);
            }
        } else {
#pragma unroll
            for (int fn = 0; fn < 4; fn++) {
                float p0 = __expf(s_acc[fn][0] - mn_lo);
                float p1 = __expf(s_acc[fn][1] - mn_lo);
                float p2 = __expf(s_acc[fn][2] - mn_hi);
                float p3 = __expf(s_acc[fn][3] - mn_hi);
                rs_lo += p0 + p1; rs_hi += p2 + p3;
                pa[fn >> 1][(fn & 1) * 2] = pack_h2(p0, p1);
                pa[fn >> 1][(fn & 1) * 2 + 1] = pack_h2(p2, p3);
            }
        }
        rs_lo += __shfl_xor_sync(~0u, rs_lo, 1);
        rs_lo += __shfl_xor_sync(~0u, rs_lo, 2);
        rs_hi += __shfl_xor_sync(~0u, rs_hi, 1);
        rs_hi += __shfl_xor_sync(~0u, rs_hi, 2);
        l_lo = l_lo * cf_lo + rs_lo;
        l_hi = l_hi * cf_hi + rs_hi;
#pragma unroll
        for (int fd = 0; fd < 8; fd++) {
            o[fd][0] *= cf_lo; o[fd][1] *= cf_lo;
            o[fd][2] *= cf_hi; o[fd][3] *= cf_hi;
        }

#pragma unroll
        for (int kb = 0; kb < 2; kb++) {
#pragma unroll
            for (int dp = 0; dp < 4; dp++) {
                uint32_t vb4[4];
                ldsm_x4_t(vb4, vaddr + kb * 16 * (ATP * 2) + dp * 32);
                mma_fp16(o[2 * dp], pa[kb], vb4[0], vb4[1]);
                mma_fp16(o[2 * dp + 1], pa[kb], vb4[2], vb4[3]);
            }
        }
    }

    pdl_trigger();

    float inv_lo = 1.0f / l_lo;
    float inv_hi = 1.0f / l_hi;
    int llo = 2 * tq_lo + p;
    int lhi = 2 * tq_hi + p;
    __half* obl = out + ((size_t)(b * LL + llo)) * DDIM + h * HDIM;
    __half* obh = out + ((size_t)(b * LL + lhi)) * DDIM + h * HDIM;
#pragma unroll
    for (int fd = 0; fd < 8; fd++) {
        int d = 8 * fd + 2 * kq;
        store2(obl + d, o[fd][0] * inv_lo, o[fd][1] * inv_lo);
        store2(obh + d, o[fd][2] * inv_hi, o[fd][3] * inv_hi);
    }
}

// ---------------------------------------------------------------------------
// Launch (PDL on launches 3..7; 1-2 normal)
// ---------------------------------------------------------------------------
extern "C" void kernel_launch(void* const* d_in, const int* in_sizes, int n_in,
                              void* d_out, int out_size) {
    const float* x     = (const float*)d_in[0];
    const float* ln1_g = (const float*)d_in[1];
    const float* ln1_b = (const float*)d_in[2];
    const float* Wqkv  = (const float*)d_in[3];
    const float* bqkv  = (const float*)d_in[4];
    const float* Wout  = (const float*)d_in[5];
    const float* bout  = (const float*)d_in[6];
    const float* ln2_g = (const float*)d_in[7];
    const float* ln2_b = (const float*)d_in[8];
    const float* W1    = (const float*)d_in[9];
    const float* b1    = (const float*)d_in[10];
    const float* W2    = (const float*)d_in[11];
    const float* b2    = (const float*)d_in[12];
    float* out = (float*)d_out;

    __half *h, *qkv, *attn, *f, *wt;
    float *x1;
    cudaGetSymbolAddress((void**)&h, g_h);
    cudaGetSymbolAddress((void**)&qkv, g_qkv);
    cudaGetSymbolAddress((void**)&attn, g_attn);
    cudaGetSymbolAddress((void**)&x1, g_x1);
    cudaGetSymbolAddress((void**)&f, g_f);
    cudaGetSymbolAddress((void**)&wt, g_wt);

    static int smem_set = 0;
    if (!smem_set) {
        cudaFuncSetAttribute(gemm_fp16<0, __half>,
                             cudaFuncAttributeMaxDynamicSharedMemorySize, FSMEM);
        cudaFuncSetAttribute(gemm_fp16<1, float>,
                             cudaFuncAttributeMaxDynamicSharedMemorySize, FSMEM);
        cudaFuncSetAttribute(gemm_fp16<2, __half>,
                             cudaFuncAttributeMaxDynamicSharedMemorySize, FSMEM);
        smem_set = 1;
    }

    cudaLaunchAttribute pdlAttr[1];
    pdlAttr[0].id = cudaLaunchAttributeProgrammaticStreamSerialization;
    pdlAttr[0].val.programmaticStreamSerializationAllowed = 1;

    cudaLaunchConfig_t cfg = {};
    cfg.stream = 0;
    cfg.attrs = pdlAttr;
    cfg.numAttrs = 1;

    // 1. LN1 + weight convert (normal launch)
    ln_conv_kernel<<<MM + NCONVB, 256>>>(x, ln1_g, ln1_b, h,
                                         Wqkv, Wout, W1, W2, wt);
    // 2. QKV = h @ Wqkv + bqkv (normal launch; pdl_wait is a no-op barrier here)
    gemm_fp16<0, __half><<<dim3(24, 32), 128, FSMEM>>>(
        h, wt + WT_QKV, bqkv, nullptr, qkv, MM, 3 * DDIM, DDIM);
    // 3. attention (PDL)
    cfg.gridDim = dim3(16, 64); cfg.blockDim = dim3(128); cfg.dynamicSmemBytes = 0;
    cudaLaunchKernelEx(&cfg, attn_flash, (const __half*)qkv, (__half*)attn);
    // 4. x1 = x + attn @ Wout + bout (PDL)
    cfg.gridDim = dim3(8, 32); cfg.blockDim = dim3(128); cfg.dynamicSmemBytes = FSMEM;
    cudaLaunchKernelEx(&cfg, gemm_fp16<1, float>,
                       (const __half*)attn, (const __half*)(wt + WT_OUT),
                       (const float*)bout, (const float*)x, (float*)x1,
                       (int)MM, (int)DDIM, (int)DDIM);
    // 5. LN2 (PDL)
    cfg.gridDim = dim3(MM); cfg.blockDim = dim3(256); cfg.dynamicSmemBytes = 0;
    cudaLaunchKernelEx(&cfg, ln_kernel,
                       (const float*)x1, (const float*)ln2_g,
                       (const float*)ln2_b, (__half*)h);
    // 6. f = gelu(h @ W1 + b1) (PDL)
    cfg.gridDim = dim3(32, 32); cfg.blockDim = dim3(128); cfg.dynamicSmemBytes = FSMEM;
    cudaLaunchKernelEx(&cfg, gemm_fp16<2, __half>,
                       (const __half*)h, (const __half*)(wt + WT_W1),
                       (const float*)b1, (const float*)nullptr, (__half*)f,
                       (int)MM, (int)(4 * DDIM), (int)DDIM);
    // 7. out = x1 + f @ W2 + b2 (PDL)
    cfg.gridDim = dim3(8, 32); cfg.blockDim = dim3(128); cfg.dynamicSmemBytes = FSMEM;
    cudaLaunchKernelEx(&cfg, gemm_fp16<1, float>,
                       (const __half*)f, (const __half*)(wt + WT_W2),
                       (const float*)b2, (const float*)x1, (float*)out,
                       (int)MM, (int)DDIM, (int)(4 * DDIM));
}

// round 17
// speedup vs baseline: 1.0351x; 1.0351x over previous
#include <cuda_runtime.h>
#include <cuda_fp16.h>
#include <cstdint>
#include <math.h>

// Problem constants
#define BB 2
#define LL 2048
#define DDIM 1024
#define HH 16
#define HDIM 64
#define MM (BB*LL)          // 4096 rows
#define WIN 512
#define DIL 2

// Scratch (device globals; no allocation allowed)
__device__ __half g_h[(size_t)MM*DDIM];          // LN output (fp16)
__device__ __half g_qkv[(size_t)MM*3*DDIM];      // QKV (fp16)
__device__ __half g_attn[(size_t)MM*DDIM];       // attention output (fp16)
__device__ __half g_x1[(size_t)MM*DDIM];         // x + attn@Wout (fp16 residual)
__device__ __half g_f[(size_t)MM*4*DDIM];        // FFN hidden (fp16)
__device__ __half g_wt[(size_t)12582912];        // fp16 weights, SAME [K,N] layout
#define WT_QKV 0
#define WT_OUT 3145728
#define WT_W1  4194304
#define WT_W2  8388608
#define WT_END 12582912
#define NCONVB 3072                               // convert blocks (WT_END/4096)

__device__ __forceinline__ void mma_fp16(float d[4], const uint32_t a[4],
                                         uint32_t b0, uint32_t b1) {
    asm volatile(
        "mma.sync.aligned.m16n8k16.row.col.f32.f16.f16.f32 "
        "{%0,%1,%2,%3}, {%4,%5,%6,%7}, {%8,%9}, {%0,%1,%2,%3};\n"
        : "+f"(d[0]), "+f"(d[1]), "+f"(d[2]), "+f"(d[3])
        : "r"(a[0]), "r"(a[1]), "r"(a[2]), "r"(a[3]),
          "r"(b0), "r"(b1));
}

__device__ __forceinline__ void ldsm_x4(uint32_t r[4], uint32_t addr) {
    asm volatile("ldmatrix.sync.aligned.m8n8.x4.shared.b16 {%0,%1,%2,%3}, [%4];"
                 : "=r"(r[0]), "=r"(r[1]), "=r"(r[2]), "=r"(r[3]) : "r"(addr));
}
__device__ __forceinline__ void ldsm_x4_t(uint32_t r[4], uint32_t addr) {
    asm volatile("ldmatrix.sync.aligned.m8n8.x4.trans.shared.b16 {%0,%1,%2,%3}, [%4];"
                 : "=r"(r[0]), "=r"(r[1]), "=r"(r[2]), "=r"(r[3]) : "r"(addr));
}

__device__ __forceinline__ float gelu_exact(float x) {
    return 0.5f * x * (1.0f + erff(x * 0.70710678118654752f));
}

__device__ __forceinline__ void cp_async16(uint32_t smem_addr, const void* gptr) {
    asm volatile("cp.async.cg.shared.global [%0], [%1], 16;\n"
                 :: "r"(smem_addr), "l"(gptr));
}
__device__ __forceinline__ void cp_commit() {
    asm volatile("cp.async.commit_group;\n");
}
__device__ __forceinline__ void cp_wait2() {
    asm volatile("cp.async.wait_group 2;\n");
}
__device__ __forceinline__ void cp_wait1() {
    asm volatile("cp.async.wait_group 1;\n");
}
__device__ __forceinline__ uint32_t smem_u32(const void* p) {
    uint32_t a;
    asm("{ .reg .u64 t; cvta.to.shared.u64 t, %1; cvt.u32.u64 %0, t; }"
        : "=r"(a) : "l"(p));
    return a;
}

__device__ __forceinline__ void store2(__half* p, float a, float b) {
    *reinterpret_cast<__half2*>(p) = __floats2half2_rn(a, b);
}
__device__ __forceinline__ void store2(float* p, float a, float b) {
    *reinterpret_cast<float2*>(p) = make_float2(a, b);
}
__device__ __forceinline__ float2 load2(const float* p) {
    return *reinterpret_cast<const float2*>(p);
}
__device__ __forceinline__ float2 load2(const __half* p) {
    return __half22float2(*reinterpret_cast<const __half2*>(p));
}

__device__ __forceinline__ uint32_t pack_h2(float a, float b) {
    __half2 h = __floats2half2_rn(a, b);
    return *reinterpret_cast<uint32_t*>(&h);
}

// ---------------------------------------------------------------------------
// Fused: LN1 (blocks 0..MM-1) + weight fp32->fp16 convert (blocks MM..)
// ---------------------------------------------------------------------------
__global__ void ln_conv_kernel(const float* __restrict__ x, const float* __restrict__ g,
                               const float* __restrict__ b, __half* __restrict__ out,
                               const float* __restrict__ s0, const float* __restrict__ s1,
                               const float* __restrict__ s2, const float* __restrict__ s3,
                               __half* __restrict__ wdst) {
    if (blockIdx.x >= MM) {
        size_t i = ((size_t)(blockIdx.x - MM) * 256 + threadIdx.x) * 16;
        const float* src; size_t base;
        if (i < WT_OUT)      { src = s0; base = 0; }
        else if (i < WT_W1)  { src = s1; base = WT_OUT; }
        else if (i < WT_W2)  { src = s2; base = WT_W1; }
        else                 { src = s3; base = WT_W2; }
        const float* sp = src + (i - base);
        float4 a0 = *reinterpret_cast<const float4*>(sp);
        float4 a1 = *reinterpret_cast<const float4*>(sp + 4);
        float4 a2 = *reinterpret_cast<const float4*>(sp + 8);
        float4 a3 = *reinterpret_cast<const float4*>(sp + 12);
        uint4 p0, p1;
        p0.x = pack_h2(a0.x, a0.y); p0.y = pack_h2(a0.z, a0.w);
        p0.z = pack_h2(a1.x, a1.y); p0.w = pack_h2(a1.z, a1.w);
        p1.x = pack_h2(a2.x, a2.y); p1.y = pack_h2(a2.z, a2.w);
        p1.z = pack_h2(a3.x, a3.y); p1.w = pack_h2(a3.z, a3.w);
        *reinterpret_cast<uint4*>(wdst + i) = p0;
        *reinterpret_cast<uint4*>(wdst + i + 8) = p1;
        return;
    }
    int row = blockIdx.x;
    int t = threadIdx.x;
    const float4 xv = reinterpret_cast<const float4*>(x + (size_t)row * DDIM)[t];

    __shared__ float warp_s[8], warp_q[8];
    __shared__ float s_mu, s_r;

    float s = xv.x + xv.y + xv.z + xv.w;
    float q = xv.x*xv.x + xv.y*xv.y + xv.z*xv.z + xv.w*xv.w;
#pragma unroll
    for (int o = 16; o; o >>= 1) {
        s += __shfl_xor_sync(~0u, s, o);
        q += __shfl_xor_sync(~0u, q, o);
    }
    if ((t & 31) == 0) { warp_s[t >> 5] = s; warp_q[t >> 5] = q; }
    __syncthreads();
    if (t == 0) {
        float S = 0.f, Q = 0.f;
#pragma unroll
        for (int i = 0; i < 8; i++) { S += warp_s[i]; Q += warp_q[i]; }
        float mu = S * (1.0f / DDIM);
        float var = Q * (1.0f / DDIM) - mu * mu;
        s_mu = mu;
        s_r = rsqrtf(var + 1e-5f);
    }
    __syncthreads();
    float mu = s_mu, r = s_r;
    float4 gv = reinterpret_cast<const float4*>(g)[t];
    float4 bv = reinterpret_cast<const float4*>(b)[t];
    uint2 pk;
    pk.x = pack_h2((xv.x - mu) * r * gv.x + bv.x, (xv.y - mu) * r * gv.y + bv.y);
    pk.y = pack_h2((xv.z - mu) * r * gv.z + bv.z, (xv.w - mu) * r * gv.w + bv.w);
    *reinterpret_cast<uint2*>(out + (size_t)row * DDIM + t * 4) = pk;
}

// ---------------------------------------------------------------------------
// LayerNorm, fp16 input (LN2 over fp16 x1)
// ---------------------------------------------------------------------------
__global__ void ln_kernel_h(const __half* __restrict__ x, const float* __restrict__ g,
                            const float* __restrict__ b, __half* __restrict__ out) {
    int row = blockIdx.x;
    int t = threadIdx.x;
    uint2 raw = reinterpret_cast<const uint2*>(x + (size_t)row * DDIM)[t];
    float2 f01 = __half22float2(*reinterpret_cast<__half2*>(&raw.x));
    float2 f23 = __half22float2(*reinterpret_cast<__half2*>(&raw.y));
    float4 xv = make_float4(f01.x, f01.y, f23.x, f23.y);

    __shared__ float warp_s[8], warp_q[8];
    __shared__ float s_mu, s_r;

    float s = xv.x + xv.y + xv.z + xv.w;
    float q = xv.x*xv.x + xv.y*xv.y + xv.z*xv.z + xv.w*xv.w;
#pragma unroll
    for (int o = 16; o; o >>= 1) {
        s += __shfl_xor_sync(~0u, s, o);
        q += __shfl_xor_sync(~0u, q, o);
    }
    if ((t & 31) == 0) { warp_s[t >> 5] = s; warp_q[t >> 5] = q; }
    __syncthreads();
    if (t == 0) {
        float S = 0.f, Q = 0.f;
#pragma unroll
        for (int i = 0; i < 8; i++) { S += warp_s[i]; Q += warp_q[i]; }
        float mu = S * (1.0f / DDIM);
        float var = Q * (1.0f / DDIM) - mu * mu;
        s_mu = mu;
        s_r = rsqrtf(var + 1e-5f);
    }
    __syncthreads();
    float mu = s_mu, r = s_r;
    float4 gv = reinterpret_cast<const float4*>(g)[t];
    float4 bv = reinterpret_cast<const float4*>(b)[t];
    uint2 pk;
    pk.x = pack_h2((xv.x - mu) * r * gv.x + bv.x, (xv.y - mu) * r * gv.y + bv.y);
    pk.y = pack_h2((xv.z - mu) * r * gv.z + bv.z, (xv.w - mu) * r * gv.w + bv.w);
    *reinterpret_cast<uint2*>(out + (size_t)row * DDIM + t * 4) = pk;
}

// ---------------------------------------------------------------------------
// FP16 GEMM (round-14 mainloop, byte-identical): C = A @ W + bias
// EPI: 0=bias, 1=bias+residual, 2=bias+GELU.  OUT/RES: __half or float.
// CTA tile 128x128x32, 128 threads (4 warps), warp tile 64x64, m16n8k16.
// 4-stage cp.async, wait_group 2, 2 CTA/SM.
// ---------------------------------------------------------------------------
#define ASTG 10240                    // A stage bytes: 128 rows * 80B
#define BSTG 8704                     // B stage bytes: 32 rows * 272B
#define FNST 4
#define FSMEM (FNST*(ASTG+BSTG))      // 75776 bytes

template <int EPI, typename OUT, typename RES>
__global__ void __launch_bounds__(128, 2)
gemm_fp16(const __half* __restrict__ A, const __half* __restrict__ W,
          const float* __restrict__ bias, const RES* __restrict__ res,
          OUT* __restrict__ C, int M, int N, int K) {
    extern __shared__ char dsm[];
    uint32_t base = smem_u32(dsm);
    uint32_t bBase = base + FNST * ASTG;

    int tid = threadIdx.x;
    int warp = tid >> 5, lane = tid & 31;
    int wm = warp & 1;     // 2 warps along M -> 64 rows
    int wn = warp >> 1;    // 2 warps along N -> 64 cols
    int mrow = lane >> 2, kq = lane & 3;
    int m0 = blockIdx.y * 128, n0 = blockIdx.x * 128;

    const __half* agp[4];
    const __half* bgp[4];
    uint32_t adst[4], bdst[4];
#pragma unroll
    for (int i = 0; i < 4; i++) {
        int ca = tid + i * 128;
        int ar = ca >> 2, ac = (ca & 3) * 8;
        agp[i] = A + (size_t)(m0 + ar) * K + ac;
        adst[i] = base + ar * 80 + ac * 2;
        int br = ca >> 4, bc = (ca & 15) * 8;
        bgp[i] = W + (size_t)br * N + n0 + bc;
        bdst[i] = bBase + br * 272 + bc * 2;
    }

    float acc[4][8][4];
#pragma unroll
    for (int i = 0; i < 4; i++)
#pragma unroll
        for (int j = 0; j < 8; j++)
#pragma unroll
            for (int k = 0; k < 4; k++) acc[i][j][k] = 0.f;

    int nk = K / 32;
    auto issue = [&](int it) {
        if (it < nk) {
            int s = it & 3;
            int k0 = it * 32;
#pragma unroll
            for (int i = 0; i < 4; i++) {
                cp_async16(adst[i] + s * ASTG, agp[i] + k0);
                cp_async16(bdst[i] + s * BSTG, bgp[i] + (size_t)k0 * N);
            }
        }
        cp_commit();
    };
    issue(0); issue(1); issue(2);

    int lrow = lane & 15;
    int lcolB = (lane >> 4) * 16;

    for (int it = 0; it < nk; it++) {
        cp_wait2();
        __syncthreads();
        issue(it + 3);
        int s = it & 3;
        uint32_t aST = base + s * ASTG;
        uint32_t bST = bBase + s * BSTG;
#pragma unroll
        for (int ks = 0; ks < 32; ks += 16) {
            uint32_t a[4][4], b[4][4];
#pragma unroll
            for (int fm = 0; fm < 4; fm++)
                ldsm_x4(a[fm], aST + (wm * 64 + fm * 16 + lrow) * 80 + ks * 2 + lcolB);
            uint32_t bRow = bST + (ks + lrow) * 272 + lcolB;
#pragma unroll
            for (int p = 0; p < 4; p++)
                ldsm_x4_t(b[p], bRow + (wn * 64 + p * 16) * 2);
#pragma unroll
            for (int fm = 0; fm < 4; fm++)
#pragma unroll
                for (int fn = 0; fn < 8; fn++)
                    mma_fp16(acc[fm][fn], a[fm],
                             b[fn >> 1][(fn & 1) * 2], b[fn >> 1][(fn & 1) * 2 + 1]);
        }
    }

#pragma unroll
    for (int fm = 0; fm < 4; fm++) {
#pragma unroll
        for (int fn = 0; fn < 8; fn++) {
            int mr = m0 + wm * 64 + fm * 16 + mrow;
            int nc = n0 + wn * 64 + fn * 8 + (kq << 1);
            float bx = bias[nc], by = bias[nc + 1];
            float v0 = acc[fm][fn][0] + bx;
            float v1 = acc[fm][fn][1] + by;
            float v2 = acc[fm][fn][2] + bx;
            float v3 = acc[fm][fn][3] + by;
            if (EPI == 1) {
                float2 r0 = load2(res + (size_t)mr * N + nc);
                float2 r1 = load2(res + (size_t)(mr + 8) * N + nc);
                v0 += r0.x; v1 += r0.y; v2 += r1.x; v3 += r1.y;
            } else if (EPI == 2) {
                v0 = gelu_exact(v0); v1 = gelu_exact(v1);
                v2 = gelu_exact(v2); v3 = gelu_exact(v3);
            }
            store2(C + (size_t)mr * N + nc, v0, v1);
            store2(C + (size_t)(mr + 8) * N + nc, v2, v3);
        }
    }
}

// ---------------------------------------------------------------------------
// Flash attention, parity streams, fp16 MMA datapath.
// 3-stage K/V cp.async ring, issue at loop top.
// Warp-uniform mask specialization, register P-packing. (round-14 config)
// ---------------------------------------------------------------------------
#define ATP 72    // smem pitch in halves (144 B)
#define KVST (32 * ATP * 2)   // bytes per K (or V) tile buffer

__global__ void __launch_bounds__(128, 4)
attn_flash(const __half* __restrict__ qkv, __half* __restrict__ out) {
    __shared__ __half Qs[64 * ATP];
    __shared__ __half Ks[3][32 * ATP];
    __shared__ __half Vs[3][32 * ATP];

    int tid = threadIdx.x;
    int w = tid >> 5, lane = tid & 31;
    int mrow = lane >> 2;
    int kq = lane & 3;

    int qt0 = blockIdx.x * 64;
    int y = blockIdx.y;
    int p = y & 1, h = (y >> 1) & 15, b = y >> 5;

    {
        int r = tid >> 1;
        int d0 = (tid & 1) * 32;
        int l = 2 * (qt0 + r) + p;
        const __half* src = qkv + ((size_t)(b * LL + l)) * (3 * DDIM) + h * HDIM + d0;
        __half* dst = Qs + r * ATP + d0;
        const __half2 sc = __float2half2_rn(0.125f);
#pragma unroll
        for (int i = 0; i < 4; i++) {
            uint4 v = reinterpret_cast<const uint4*>(src)[i];
            __half2* hv = reinterpret_cast<__half2*>(&v);
#pragma unroll
            for (int j = 0; j < 4; j++) hv[j] = __hmul2(hv[j], sc);
            reinterpret_cast<uint4*>(dst)[i] = v;
        }
    }

    int ktbeg = qt0 - 256; if (ktbeg < 0) ktbeg = 0;
    int nt = (qt0 + 32 - ktbeg) / 32 + 1;

    int kvr0 = tid >> 3;
    int kvc = (tid & 7) * 16;
    uint32_t ksb = smem_u32(Ks);
    uint32_t vsb = smem_u32(Vs);
    auto issue_kv = [&](int ti) {
        if (ti < nt) {
            int s = ti % 3;
            int kt0 = ktbeg + ti * 32;
#pragma unroll
            for (int half = 0; half < 2; half++) {
                int r = kvr0 + half * 16;
                int lk = 2 * (kt0 + r) + p;
                const __half* kb = qkv + ((size_t)(b * LL + lk)) * (3 * DDIM)
                                   + DDIM + h * HDIM;
                cp_async16(ksb + s * KVST + r * 144 + kvc,
                           reinterpret_cast<const char*>(kb) + kvc);
                cp_async16(vsb + s * KVST + r * 144 + kvc,
                           reinterpret_cast<const char*>(kb + DDIM) + kvc);
            }
        }
        cp_commit();
    };
    issue_kv(0);
    issue_kv(1);

    __syncthreads();   // Q tile ready

    uint32_t qa[4][4];
    {
        uint32_t qb = smem_u32(Qs) + (w * 16 + (lane & 15)) * (ATP * 2) + (lane >> 4) * 16;
#pragma unroll
        for (int i = 0; i < 4; i++) ldsm_x4(qa[i], qb + i * 32);
    }

    float m_lo = -1e30f, m_hi = -1e30f, l_lo = 0.f, l_hi = 0.f;
    float o[8][4];
#pragma unroll
    for (int i = 0; i < 8; i++)
#pragma unroll
        for (int j = 0; j < 4; j++) o[i][j] = 0.f;

    int tq_lo = qt0 + 16 * w + mrow;
    int tq_hi = tq_lo + 8;

    uint32_t kaddrO = ((lane >> 4) * 8 + (lane & 7)) * (ATP * 2) + ((lane >> 3) & 1) * 16;
    uint32_t vaddrO = (lane & 15) * (ATP * 2) + (lane >> 4) * 16;

    for (int ti = 0; ti < nt; ti++) {
        int kt0 = ktbeg + ti * 32;
        int s = ti % 3;
        cp_wait1();
        __syncthreads();           // orders prev iter's reads before new writes
        issue_kv(ti + 2);          // writes stage (ti+2)%3 — disjoint from ti, ti+1
        uint32_t kaddr = ksb + s * KVST + kaddrO;
        uint32_t vaddr = vsb + s * KVST + vaddrO;

        float s_acc[4][4];
#pragma unroll
        for (int fn = 0; fn < 4; fn++)
#pragma unroll
            for (int j = 0; j < 4; j++) s_acc[fn][j] = 0.f;
#pragma unroll
        for (int i = 0; i < 4; i++) {
            uint32_t kb0[4], kb1[4];
            ldsm_x4(kb0, kaddr + i * 32);
            ldsm_x4(kb1, kaddr + 16 * (ATP * 2) + i * 32);
            mma_fp16(s_acc[0], qa[i], kb0[0], kb0[1]);
            mma_fp16(s_acc[1], qa[i], kb0[2], kb0[3]);
            mma_fp16(s_acc[2], qa[i], kb1[0], kb1[1]);
            mma_fp16(s_acc[3], qa[i], kb1[2], kb1[3]);
        }

        bool needmask = (kt0 > qt0 + 16 * w - 31) || (kt0 < qt0 + 16 * w - 241);

        float mt_lo = -1e30f, mt_hi = -1e30f;
        if (needmask) {
#pragma unroll
            for (int fn = 0; fn < 4; fn++) {
#pragma unroll
                for (int j = 0; j < 2; j++) {
                    int tk = kt0 + 8 * fn + 2 * kq + j;
                    if (!(tk <= tq_lo && tq_lo - tk <= 256)) s_acc[fn][j] = -1e30f;
                    if (!(tk <= tq_hi && tq_hi - tk <= 256)) s_acc[fn][2 + j] = -1e30f;
                    mt_lo = fmaxf(mt_lo, s_acc[fn][j]);
                    mt_hi = fmaxf(mt_hi, s_acc[fn][2 + j]);
                }
            }
        } else {
#pragma unroll
            for (int fn = 0; fn < 4; fn++) {
                mt_lo = fmaxf(mt_lo, fmaxf(s_acc[fn][0], s_acc[fn][1]));
                mt_hi = fmaxf(mt_hi, fmaxf(s_acc[fn][2], s_acc[fn][3]));
            }
        }
        mt_lo = fmaxf(mt_lo, __shfl_xor_sync(~0u, mt_lo, 1));
        mt_lo = fmaxf(mt_lo, __shfl_xor_sync(~0u, mt_lo, 2));
        mt_hi = fmaxf(mt_hi, __shfl_xor_sync(~0u, mt_hi, 1));
        mt_hi = fmaxf(mt_hi, __shfl_xor_sync(~0u, mt_hi, 2));
        float mn_lo = fmaxf(m_lo, mt_lo);
        float mn_hi = fmaxf(m_hi, mt_hi);
        float cf_lo = __expf(m_lo - mn_lo);
        float cf_hi = __expf(m_hi - mn_hi);
        m_lo = mn_lo; m_hi = mn_hi;

        float rs_lo = 0.f, rs_hi = 0.f;
        uint32_t pa[2][4];
        if (needmask) {
#pragma unroll
            for (int fn = 0; fn < 4; fn++) {
                float p0 = __expf(s_acc[fn][0] - mn_lo);
                float p1 = __expf(s_acc[fn][1] - mn_lo);
                float p2 = __expf(s_acc[fn][2] - mn_hi);
                float p3 = __expf(s_acc[fn][3] - mn_hi);
                if (s_acc[fn][0] < -1e29f) p0 = 0.f;
                if (s_acc[fn][1] < -1e29f) p1 = 0.f;
                if (s_acc[fn][2] < -1e29f) p2 = 0.f;
                if (s_acc[fn][3] < -1e29f) p3 = 0.f;
                rs_lo += p0 + p1; rs_hi += p2 + p3;
                pa[fn >> 1][(fn & 1) * 2] = pack_h2(p0, p1);
                pa[fn >> 1][(fn & 1) * 2 + 1] = pack_h2(p2, p3);
            }
        } else {
#pragma unroll
            for (int fn = 0; fn < 4; fn++) {
                float p0 = __expf(s_acc[fn][0] - mn_lo);
                float p1 = __expf(s_acc[fn][1] - mn_lo);
                float p2 = __expf(s_acc[fn][2] - mn_hi);
                float p3 = __expf(s_acc[fn][3] - mn_hi);
                rs_lo += p0 + p1; rs_hi += p2 + p3;
                pa[fn >> 1][(fn & 1) * 2] = pack_h2(p0, p1);
                pa[fn >> 1][(fn & 1) * 2 + 1] = pack_h2(p2, p3);
            }
        }
        rs_lo += __shfl_xor_sync(~0u, rs_lo, 1);
        rs_lo += __shfl_xor_sync(~0u, rs_lo, 2);
        rs_hi += __shfl_xor_sync(~0u, rs_hi, 1);
        rs_hi += __shfl_xor_sync(~0u, rs_hi, 2);
        l_lo = l_lo * cf_lo + rs_lo;
        l_hi = l_hi * cf_hi + rs_hi;
#pragma unroll
        for (int fd = 0; fd < 8; fd++) {
            o[fd][0] *= cf_lo; o[fd][1] *= cf_lo;
            o[fd][2] *= cf_hi; o[fd][3] *= cf_hi;
        }

#pragma unroll
        for (int kb = 0; kb < 2; kb++) {
#pragma unroll
            for (int dp = 0; dp < 4; dp++) {
                uint32_t vb4[4];
                ldsm_x4_t(vb4, vaddr + kb * 16 * (ATP * 2) + dp * 32);
                mma_fp16(o[2 * dp], pa[kb], vb4[0], vb4[1]);
                mma_fp16(o[2 * dp + 1], pa[kb], vb4[2], vb4[3]);
            }
        }
    }

    float inv_lo = 1.0f / l_lo;
    float inv_hi = 1.0f / l_hi;
    int llo = 2 * tq_lo + p;
    int lhi = 2 * tq_hi + p;
    __half* obl = out + ((size_t)(b * LL + llo)) * DDIM + h * HDIM;
    __half* obh = out + ((size_t)(b * LL + lhi)) * DDIM + h * HDIM;
#pragma unroll
    for (int fd = 0; fd < 8; fd++) {
        int d = 8 * fd + 2 * kq;
        store2(obl + d, o[fd][0] * inv_lo, o[fd][1] * inv_lo);
        store2(obh + d, o[fd][2] * inv_hi, o[fd][3] * inv_hi);
    }
}

// ---------------------------------------------------------------------------
// Launch (plain launches; round-14 structure; x1 in fp16)
// ---------------------------------------------------------------------------
extern "C" void kernel_launch(void* const* d_in, const int* in_sizes, int n_in,
                              void* d_out, int out_size) {
    const float* x     = (const float*)d_in[0];
    const float* ln1_g = (const float*)d_in[1];
    const float* ln1_b = (const float*)d_in[2];
    const float* Wqkv  = (const float*)d_in[3];
    const float* bqkv  = (const float*)d_in[4];
    const float* Wout  = (const float*)d_in[5];
    const float* bout  = (const float*)d_in[6];
    const float* ln2_g = (const float*)d_in[7];
    const float* ln2_b = (const float*)d_in[8];
    const float* W1    = (const float*)d_in[9];
    const float* b1    = (const float*)d_in[10];
    const float* W2    = (const float*)d_in[11];
    const float* b2    = (const float*)d_in[12];
    float* out = (float*)d_out;

    __half *h, *qkv, *attn, *f, *wt, *x1;
    cudaGetSymbolAddress((void**)&h, g_h);
    cudaGetSymbolAddress((void**)&qkv, g_qkv);
    cudaGetSymbolAddress((void**)&attn, g_attn);
    cudaGetSymbolAddress((void**)&x1, g_x1);
    cudaGetSymbolAddress((void**)&f, g_f);
    cudaGetSymbolAddress((void**)&wt, g_wt);

    static int smem_set = 0;
    if (!smem_set) {
        cudaFuncSetAttribute((const void*)gemm_fp16<0, __half, float>,
                             cudaFuncAttributeMaxDynamicSharedMemorySize, FSMEM);
        cudaFuncSetAttribute((const void*)gemm_fp16<1, __half, float>,
                             cudaFuncAttributeMaxDynamicSharedMemorySize, FSMEM);
        cudaFuncSetAttribute((const void*)gemm_fp16<1, float, __half>,
                             cudaFuncAttributeMaxDynamicSharedMemorySize, FSMEM);
        cudaFuncSetAttribute((const void*)gemm_fp16<2, __half, float>,
                             cudaFuncAttributeMaxDynamicSharedMemorySize, FSMEM);
        smem_set = 1;
    }

    // 1. LN1 + weight convert (fused, independent work)
    ln_conv_kernel<<<MM + NCONVB, 256>>>(x, ln1_g, ln1_b, h,
                                         Wqkv, Wout, W1, W2, wt);
    // 2. QKV = h @ Wqkv + bqkv
    gemm_fp16<0, __half, float><<<dim3(24, 32), 128, FSMEM>>>(
        h, wt + WT_QKV, bqkv, (const float*)nullptr, qkv, MM, 3 * DDIM, DDIM);
    // 3. attention
    attn_flash<<<dim3(16, 64), 128>>>(qkv, attn);
    // 4. x1 = x + attn @ Wout + bout   (fp16 out)
    gemm_fp16<1, __half, float><<<dim3(8, 32), 128, FSMEM>>>(
        attn, wt + WT_OUT, bout, x, x1, MM, DDIM, DDIM);
    // 5. LN2 (fp16 input)
    ln_kernel_h<<<MM, 256>>>(x1, ln2_g, ln2_b, h);
    // 6. f = gelu(h @ W1 + b1)
    gemm_fp16<2, __half, float><<<dim3(32, 32), 128, FSMEM>>>(
        h, wt + WT_W1, b1, (const float*)nullptr, f, MM, 4 * DDIM, DDIM);
    // 7. out = x1 + f @ W2 + b2        (fp16 residual, fp32 out)
    gemm_fp16<1, float, __half><<<dim3(8, 32), 128, FSMEM>>>(
        f, wt + WT_W2, b2, x1, out, MM, DDIM, 4 * DDIM);
}